// round 14
// baseline (speedup 1.0000x reference)
#include <cuda_runtime.h>
#include <cuda_bf16.h>

// Problem constants
#define B_  16
#define C_  4096
#define HD_ 1024   // H*D
#define F_  1024

// Tiling: grid = (NF, NK) = 512 blocks, 128 threads, one f-column per thread
#define NF  8
#define TFX 128
#define NK  64
#define TK  16

// Monotonic per-f-tile counters (never reset -> graph-replay-safe).
__device__ unsigned int g_done[NF];     // zero-init at module load
__device__ unsigned int g_ticket[NF];

__device__ __forceinline__ unsigned ld_acq_u32(const unsigned* p) {
    unsigned v;
    asm volatile("ld.global.acquire.gpu.u32 %0, [%1];" : "=r"(v) : "l"(p));
    return v;
}
__device__ __forceinline__ void redg_add_f32(float* p, float v) {
    asm volatile("red.global.add.f32 [%0], %1;" :: "l"(p), "f"(v) : "memory");
}
__device__ __forceinline__ void ffma2(unsigned long long& d,
                                      unsigned long long a,
                                      unsigned long long b) {
    asm("fma.rn.f32x2 %0, %1, %2, %0;" : "+l"(d) : "l"(a), "l"(b));
}
__device__ __forceinline__ unsigned long long pack2(float lo, float hi) {
    unsigned long long r;
    asm("mov.b64 %0, {%1, %2};" : "=l"(r) : "f"(lo), "f"(hi));
    return r;
}
__device__ __forceinline__ float unpack_sum(unsigned long long v) {
    float lo, hi;
    asm("mov.b64 {%0, %1}, %2;" : "=f"(lo), "=f"(hi) : "l"(v));
    return lo + hi;
}
__device__ __forceinline__ float bfr(float v) {   // bf16 round-trip
    return __bfloat162float(__float2bfloat16(v));
}

// ---------------------------------------------------------------------------
// Single kernel. Attention degenerates (T=1 causal => softmax one-hot at
// rotated position 0) to v_sel[b] = bf16(kv_value[b, start_b]) -- or the
// fresh x@wv+bv row iff idx==0. Then y = v_sel @ wo + bo via 64-way split-K.
// wo loads issue FIRST (max MLP from cycle ~10). Threads 0..63 gather one
// float4 each straight off kv_idx. ONE barrier. Early-release epilogue:
// kx==0 block publishes bias into y immediately and bumps done[fx]; all
// blocks fire red.global.add partials. Waiter spin = tight acquire poll.
// ---------------------------------------------------------------------------
__global__ void __launch_bounds__(TFX)
fused_kernel(const float* __restrict__ x,
             const int*   __restrict__ kv_idx,
             const float* __restrict__ kv_value,
             const float* __restrict__ wv,
             const float* __restrict__ bv,
             const float* __restrict__ wo,
             const float* __restrict__ bo,
             float* __restrict__ y)
{
    const int fx  = blockIdx.x;
    const int kx  = blockIdx.y;
    const int tid = threadIdx.x;
    const int k0  = kx * TK;
    const int f   = fx * TFX + tid;

    __shared__ float    vs[B_][TK];         // bf16-rounded selected v slice
    __shared__ int      s_start[B_];
    __shared__ int      s_new[B_];
    __shared__ unsigned s_target;

    // ---- FIRST: all 16 wo loads in flight ----
    float w[TK];
    #pragma unroll
    for (int k = 0; k < TK; k++)
        w[k] = __ldg(&wo[(size_t)(k0 + k) * F_ + f]);

    // ---- Gather chain: threads 0..63 fetch one float4 each ----
    const int  gb = tid >> 2;               // b (valid for tid < 64)
    const int  gq = tid & 3;                // float4 index within TK slice
    bool use_new = false;
    int  start   = 0;
    float4 gv = make_float4(0.f, 0.f, 0.f, 0.f);
    if (tid < B_ * TK / 4) {                // 64 gather threads
        const int idxv    = __ldg(&kv_idx[gb]);
        const int new_idx = idxv + 1;
        start   = (new_idx <= C_) ? 0 : (new_idx & (C_ - 1));
        use_new = (start == (idxv & (C_ - 1)));   // only when idx==0
        if (!use_new)
            gv = __ldg(reinterpret_cast<const float4*>(
                     kv_value + ((size_t)gb * C_ + start) * HD_ + k0) + gq);
    }

    // ---- Writer publishes bias into y immediately (overwrites poison) ----
    if (kx == 0) {
        const float bias = __ldg(&bo[f]);
        #pragma unroll
        for (int b = 0; b < B_; b++)
            y[b * F_ + f] = bias;
        __threadfence();            // release bias stores device-wide
    } else if (tid == 0) {
        s_target = atomicAdd(&g_ticket[fx], 1u) / (NK - 1) + 1u;
    }

    // ---- Store gathered slice (bf16-rounded) + bookkeeping ----
    if (tid < B_ * TK / 4) {
        if (!use_new) {
            float4 r;
            r.x = bfr(gv.x); r.y = bfr(gv.y); r.z = bfr(gv.z); r.w = bfr(gv.w);
            *reinterpret_cast<float4*>(&vs[gb][gq * 4]) = r;
        }
        if (gq == 0) {
            s_new[gb]   = use_new;
            s_start[gb] = start;
        }
    }

    // ONE barrier: vs visible + any_new flag + writer block fully fenced
    const int any_new = __syncthreads_or(use_new ? 1 : 0);

    if (kx == 0 && tid == 0)
        atomicAdd(&g_done[fx], 1u);          // release after block fenced

    if (any_new) {      // never taken for this input; kept for correctness
        for (int b = 0; b < B_; b++) {
            if (s_new[b] && tid < TK) {
                const int j = k0 + tid;
                float acc = bv[j];
                for (int ff = 0; ff < F_; ff++)
                    acc = fmaf(__ldg(&x[b * F_ + ff]),
                               __ldg(&wv[(size_t)ff * HD_ + j]), acc);
                vs[b][tid] = bfr(acc);
            }
        }
        __syncthreads();
    }

    // ---- Main loop: pure LDS + packed f32x2 FMA (wo already in regs) ----
    unsigned long long acc2[B_];
    #pragma unroll
    for (int b = 0; b < B_; b++) acc2[b] = 0ull;

    #pragma unroll
    for (int k4 = 0; k4 < TK; k4 += 4) {
        const unsigned long long wA = pack2(w[k4 + 0], w[k4 + 1]);
        const unsigned long long wB = pack2(w[k4 + 2], w[k4 + 3]);
        #pragma unroll
        for (int b = 0; b < B_; b++) {
            const float4 v = *reinterpret_cast<const float4*>(&vs[b][k4]);
            ffma2(acc2[b], pack2(v.x, v.y), wA);
            ffma2(acc2[b], pack2(v.z, v.w), wB);
        }
    }

    // ---- Epilogue: ensure bias published, then fire REDG partials ----
    if (kx != 0) {
        if (tid == 0) {
            // Tight acquire poll: expected wait ~0 (writers launch first).
            while (ld_acq_u32(&g_done[fx]) < s_target) { }
        }
        __syncthreads();            // all threads ordered after acquire
    }
    // Writer: same-thread store->red on same address is program-ordered.
    #pragma unroll
    for (int b = 0; b < B_; b++)
        redg_add_f32(&y[b * F_ + f], unpack_sum(acc2[b]));
}

// ---------------------------------------------------------------------------
// Inputs (metadata order): x, mask, kv_idx, kv_key, kv_value,
//                          wq, bq, wk, bk, wv, bv, wo, bo
// ---------------------------------------------------------------------------
extern "C" void kernel_launch(void* const* d_in, const int* in_sizes, int n_in,
                              void* d_out, int out_size)
{
    const float* x        = (const float*)d_in[0];
    const int*   kv_idx   = (const int*)  d_in[2];
    const float* kv_value = (const float*)d_in[4];
    const float* wv       = (const float*)d_in[9];
    const float* bv       = (const float*)d_in[10];
    const float* wo       = (const float*)d_in[11];
    const float* bo       = (const float*)d_in[12];
    float* y = (float*)d_out;

    fused_kernel<<<dim3(NF, NK), TFX>>>(x, kv_idx, kv_value,
                                        wv, bv, wo, bo, y);
}

// round 15
// speedup vs baseline: 1.0109x; 1.0109x over previous
#include <cuda_runtime.h>
#include <cuda_bf16.h>

// Problem constants
#define B_  16
#define C_  4096
#define HD_ 1024   // H*D
#define F_  1024

// Tiling: grid = (NF, NK) = 256 blocks, 128 threads, one f-column per thread
#define NF  8
#define TFX 128
#define NK  32
#define TK  32

// Monotonic per-f-tile counters (never reset -> graph-replay-safe).
__device__ unsigned int g_done[NF];     // zero-init at module load
__device__ unsigned int g_ticket[NF];

__device__ __forceinline__ unsigned ld_acq_u32(const unsigned* p) {
    unsigned v;
    asm volatile("ld.global.acquire.gpu.u32 %0, [%1];" : "=r"(v) : "l"(p));
    return v;
}
__device__ __forceinline__ void redg_add_v4(float* p, float4 v) {
    asm volatile("red.global.add.v4.f32 [%0], {%1, %2, %3, %4};"
                 :: "l"(p), "f"(v.x), "f"(v.y), "f"(v.z), "f"(v.w)
                 : "memory");
}
__device__ __forceinline__ void ffma2(unsigned long long& d,
                                      unsigned long long a,
                                      unsigned long long b) {
    asm("fma.rn.f32x2 %0, %1, %2, %0;" : "+l"(d) : "l"(a), "l"(b));
}
__device__ __forceinline__ unsigned long long pack2(float lo, float hi) {
    unsigned long long r;
    asm("mov.b64 %0, {%1, %2};" : "=l"(r) : "f"(lo), "f"(hi));
    return r;
}
__device__ __forceinline__ float unpack_sum(unsigned long long v) {
    float lo, hi;
    asm("mov.b64 {%0, %1}, %2;" : "=f"(lo), "=f"(hi) : "l"(v));
    return lo + hi;
}
__device__ __forceinline__ float bfr(float v) {   // bf16 round-trip
    return __bfloat162float(__float2bfloat16(v));
}

// ---------------------------------------------------------------------------
// Single kernel. Attention degenerates (T=1 causal => softmax one-hot at
// rotated position 0) to v_sel[b] = bf16(kv_value[b, start_b]) -- or the
// fresh x@wv+bv row iff idx==0. Then y = v_sel @ wo + bo via 32-way split-K.
// Front-end: per-thread direct kv_idx load + single float4 gather; ONE
// barrier before the FMA loop. Epilogue: early-release bias publish (kx==0
// block, first thing) + smem transpose + VECTORIZED red.global.add.v4.f32
// (4 REDG ops/thread instead of 16 -> 4x less LTS atomic serialization).
// ---------------------------------------------------------------------------
__global__ void __launch_bounds__(TFX)
fused_kernel(const float* __restrict__ x,
             const int*   __restrict__ kv_idx,
             const float* __restrict__ kv_value,
             const float* __restrict__ wv,
             const float* __restrict__ bv,
             const float* __restrict__ wo,
             const float* __restrict__ bo,
             float* __restrict__ y)
{
    const int fx  = blockIdx.x;
    const int kx  = blockIdx.y;
    const int tid = threadIdx.x;
    const int k0  = kx * TK;
    const int f   = fx * TFX + tid;

    __shared__ float    vs[B_][TK];         // bf16-rounded selected v slice
    __shared__ float    xb[B_][TFX];        // acc transpose buffer, 8 KB
    __shared__ int      s_start[B_];
    __shared__ int      s_new[B_];
    __shared__ unsigned s_target;

    // ---- Critical path first: this thread's single float4 gather ----
    const int  gb      = tid >> 3;          // b this thread gathers for
    const int  gq      = tid & 7;           // float4 index within TK slice
    const int  idxv    = __ldg(&kv_idx[gb]);
    const int  new_idx = idxv + 1;
    const int  start   = (new_idx <= C_) ? 0 : (new_idx & (C_ - 1));
    const bool use_new = (start == (idxv & (C_ - 1)));   // only when idx==0

    float4 gv = make_float4(0.f, 0.f, 0.f, 0.f);
    if (!use_new)
        gv = __ldg(reinterpret_cast<const float4*>(
                 kv_value + ((size_t)gb * C_ + start) * HD_ + k0) + gq);

    // ---- Writer publishes bias into y immediately (overwrites poison) ----
    if (kx == 0) {
        const float bias = __ldg(&bo[f]);
        #pragma unroll
        for (int b = 0; b < B_; b++)
            y[b * F_ + f] = bias;
        __threadfence();            // release bias stores device-wide
    } else if (tid == 0) {
        s_target = atomicAdd(&g_ticket[fx], 1u) / (NK - 1) + 1u;
    }

    // ---- Hoisted wo loads: overlap with gather latency ----
    float w[TK];
    #pragma unroll
    for (int k = 0; k < TK; k++)
        w[k] = __ldg(&wo[(size_t)(k0 + k) * F_ + f]);

    // ---- Store gathered slice (bf16-rounded) + bookkeeping ----
    if (!use_new) {
        float4 r;
        r.x = bfr(gv.x); r.y = bfr(gv.y); r.z = bfr(gv.z); r.w = bfr(gv.w);
        *reinterpret_cast<float4*>(&vs[gb][gq * 4]) = r;
    }
    if (gq == 0) {
        s_new[gb]   = use_new;
        s_start[gb] = start;
    }

    // ONE barrier: vs visible + any_new flag + writer block fully fenced
    const int any_new = __syncthreads_or(use_new ? 1 : 0);

    if (kx == 0 && tid == 0)
        atomicAdd(&g_done[fx], 1u);          // release after block fenced

    if (any_new) {      // never taken for this input; kept for correctness
        for (int b = 0; b < B_; b++) {
            if (s_new[b] && tid < TK) {
                const int j = k0 + tid;
                float acc = bv[j];
                for (int ff = 0; ff < F_; ff++)
                    acc = fmaf(__ldg(&x[b * F_ + ff]),
                               __ldg(&wv[(size_t)ff * HD_ + j]), acc);
                vs[b][tid] = bfr(acc);
            }
        }
        __syncthreads();
    }

    // ---- Main loop: pure LDS + packed f32x2 FMA (wo already in regs) ----
    unsigned long long acc2[B_];
    #pragma unroll
    for (int b = 0; b < B_; b++) acc2[b] = 0ull;

    #pragma unroll
    for (int k4 = 0; k4 < TK; k4 += 4) {
        const unsigned long long wA = pack2(w[k4 + 0], w[k4 + 1]);
        const unsigned long long wB = pack2(w[k4 + 2], w[k4 + 3]);
        #pragma unroll
        for (int b = 0; b < B_; b++) {
            const float4 v = *reinterpret_cast<const float4*>(&vs[b][k4]);
            ffma2(acc2[b], pack2(v.x, v.y), wA);
            ffma2(acc2[b], pack2(v.z, v.w), wB);
        }
    }

    // ---- Transpose accs to smem so REDGs can be f-contiguous float4 ----
    #pragma unroll
    for (int b = 0; b < B_; b++)
        xb[b][tid] = unpack_sum(acc2[b]);    // conflict-free STS.32

    if (kx != 0 && tid == 0) {
        while (ld_acq_u32(&g_done[fx]) < s_target)   // usually 1 read
            __nanosleep(32);
    }
    __syncthreads();    // transpose visible + bias-publish ordered (block
                        // scope via barrier; device scope via done-flag)

    // ---- Vectorized reduction: 4 x red.global.add.v4.f32 per thread ----
    #pragma unroll
    for (int it = 0; it < 4; it++) {
        const int item = it * TFX + tid;     // 0..511 over (b, f-quad)
        const int b    = item >> 5;
        const int fg   = item & 31;
        const float4 v = *reinterpret_cast<const float4*>(&xb[b][fg * 4]);
        redg_add_v4(&y[b * F_ + fx * TFX + fg * 4], v);
    }
}

// ---------------------------------------------------------------------------
// Inputs (metadata order): x, mask, kv_idx, kv_key, kv_value,
//                          wq, bq, wk, bk, wv, bv, wo, bo
// ---------------------------------------------------------------------------
extern "C" void kernel_launch(void* const* d_in, const int* in_sizes, int n_in,
                              void* d_out, int out_size)
{
    const float* x        = (const float*)d_in[0];
    const int*   kv_idx   = (const int*)  d_in[2];
    const float* kv_value = (const float*)d_in[4];
    const float* wv       = (const float*)d_in[9];
    const float* bv       = (const float*)d_in[10];
    const float* wo       = (const float*)d_in[11];
    const float* bo       = (const float*)d_in[12];
    float* y = (float*)d_out;

    fused_kernel<<<dim3(NF, NK), TFX>>>(x, kv_idx, kv_value,
                                        wv, bv, wo, bo, y);
}

// round 16
// speedup vs baseline: 1.0734x; 1.0618x over previous
#include <cuda_runtime.h>
#include <cuda_bf16.h>

// Problem constants
#define B_  16
#define C_  4096
#define HD_ 1024   // H*D
#define F_  1024

// Tiling: grid = (NF, NK) = 512 blocks, 128 threads, one f-column per thread
#define NF  8
#define TFX 128
#define NK  64
#define TK  16

// Monotonic per-f-tile counters (never reset -> graph-replay-safe).
__device__ unsigned int g_done[NF];     // zero-init at module load
__device__ unsigned int g_ticket[NF];

__device__ __forceinline__ unsigned ld_acq_u32(const unsigned* p) {
    unsigned v;
    asm volatile("ld.global.acquire.gpu.u32 %0, [%1];" : "=r"(v) : "l"(p));
    return v;
}
__device__ __forceinline__ void redg_add_v4(float* p, float4 v) {
    asm volatile("red.global.add.v4.f32 [%0], {%1, %2, %3, %4};"
                 :: "l"(p), "f"(v.x), "f"(v.y), "f"(v.z), "f"(v.w)
                 : "memory");
}
__device__ __forceinline__ void ffma2(unsigned long long& d,
                                      unsigned long long a,
                                      unsigned long long b) {
    asm("fma.rn.f32x2 %0, %1, %2, %0;" : "+l"(d) : "l"(a), "l"(b));
}
__device__ __forceinline__ unsigned long long pack2(float lo, float hi) {
    unsigned long long r;
    asm("mov.b64 %0, {%1, %2};" : "=l"(r) : "f"(lo), "f"(hi));
    return r;
}
__device__ __forceinline__ float unpack_sum(unsigned long long v) {
    float lo, hi;
    asm("mov.b64 {%0, %1}, %2;" : "=f"(lo), "=f"(hi) : "l"(v));
    return lo + hi;
}
__device__ __forceinline__ float bfr(float v) {   // bf16 round-trip
    return __bfloat162float(__float2bfloat16(v));
}

// ---------------------------------------------------------------------------
// Single kernel. Attention degenerates (T=1 causal => softmax one-hot at
// rotated position 0) to v_sel[b] = bf16(kv_value[b, start_b]) -- or the
// fresh x@wv+bv row iff idx==0. Then y = v_sel @ wo + bo via 64-way split-K.
// Front-end: threads 0..63 gather one float4 each straight off kv_idx; ONE
// barrier before the FMA loop. Epilogue: early-release bias publish (kx==0
// block, first thing) + smem transpose + VECTORIZED red.global.add.v4.f32
// (4 REDG ops/thread -> minimal LTS atomic serialization tail).
// ---------------------------------------------------------------------------
__global__ void __launch_bounds__(TFX)
fused_kernel(const float* __restrict__ x,
             const int*   __restrict__ kv_idx,
             const float* __restrict__ kv_value,
             const float* __restrict__ wv,
             const float* __restrict__ bv,
             const float* __restrict__ wo,
             const float* __restrict__ bo,
             float* __restrict__ y)
{
    const int fx  = blockIdx.x;
    const int kx  = blockIdx.y;
    const int tid = threadIdx.x;
    const int k0  = kx * TK;
    const int f   = fx * TFX + tid;

    __shared__ float    vs[B_][TK];         // bf16-rounded selected v slice
    __shared__ float    xb[B_][TFX];        // acc transpose buffer, 8 KB
    __shared__ int      s_start[B_];
    __shared__ int      s_new[B_];
    __shared__ unsigned s_target;

    // ---- Critical path first: threads 0..63 gather one float4 each ----
    const int gb = tid >> 2;                // b (valid for tid < 64)
    const int gq = tid & 3;                 // float4 index within TK slice
    bool use_new = false;
    int  start   = 0;
    float4 gv = make_float4(0.f, 0.f, 0.f, 0.f);
    if (tid < B_ * TK / 4) {                // 64 gather threads
        const int idxv    = __ldg(&kv_idx[gb]);
        const int new_idx = idxv + 1;
        start   = (new_idx <= C_) ? 0 : (new_idx & (C_ - 1));
        use_new = (start == (idxv & (C_ - 1)));   // only when idx==0
        if (!use_new)
            gv = __ldg(reinterpret_cast<const float4*>(
                     kv_value + ((size_t)gb * C_ + start) * HD_ + k0) + gq);
    }

    // ---- Writer publishes bias into y immediately (overwrites poison) ----
    if (kx == 0) {
        const float bias = __ldg(&bo[f]);
        #pragma unroll
        for (int b = 0; b < B_; b++)
            y[b * F_ + f] = bias;
        __threadfence();            // release bias stores device-wide
    } else if (tid == 0) {
        s_target = atomicAdd(&g_ticket[fx], 1u) / (NK - 1) + 1u;
    }

    // ---- Hoisted wo loads: overlap with gather latency ----
    float w[TK];
    #pragma unroll
    for (int k = 0; k < TK; k++)
        w[k] = __ldg(&wo[(size_t)(k0 + k) * F_ + f]);

    // ---- Store gathered slice (bf16-rounded) + bookkeeping ----
    if (tid < B_ * TK / 4) {
        if (!use_new) {
            float4 r;
            r.x = bfr(gv.x); r.y = bfr(gv.y); r.z = bfr(gv.z); r.w = bfr(gv.w);
            *reinterpret_cast<float4*>(&vs[gb][gq * 4]) = r;
        }
        if (gq == 0) {
            s_new[gb]   = use_new;
            s_start[gb] = start;
        }
    }

    // ONE barrier: vs visible + any_new flag + writer block fully fenced
    const int any_new = __syncthreads_or(use_new ? 1 : 0);

    if (kx == 0 && tid == 0)
        atomicAdd(&g_done[fx], 1u);          // release after block fenced

    if (any_new) {      // never taken for this input; kept for correctness
        for (int b = 0; b < B_; b++) {
            if (s_new[b] && tid < TK) {
                const int j = k0 + tid;
                float acc = bv[j];
                for (int ff = 0; ff < F_; ff++)
                    acc = fmaf(__ldg(&x[b * F_ + ff]),
                               __ldg(&wv[(size_t)ff * HD_ + j]), acc);
                vs[b][tid] = bfr(acc);
            }
        }
        __syncthreads();
    }

    // ---- Main loop: pure LDS + packed f32x2 FMA (wo already in regs) ----
    unsigned long long acc2[B_];
    #pragma unroll
    for (int b = 0; b < B_; b++) acc2[b] = 0ull;

    #pragma unroll
    for (int k4 = 0; k4 < TK; k4 += 4) {
        const unsigned long long wA = pack2(w[k4 + 0], w[k4 + 1]);
        const unsigned long long wB = pack2(w[k4 + 2], w[k4 + 3]);
        #pragma unroll
        for (int b = 0; b < B_; b++) {
            const float4 v = *reinterpret_cast<const float4*>(&vs[b][k4]);
            ffma2(acc2[b], pack2(v.x, v.y), wA);
            ffma2(acc2[b], pack2(v.z, v.w), wB);
        }
    }

    // ---- Transpose accs to smem so REDGs can be f-contiguous float4 ----
    #pragma unroll
    for (int b = 0; b < B_; b++)
        xb[b][tid] = unpack_sum(acc2[b]);    // conflict-free STS.32

    if (kx != 0 && tid == 0) {
        while (ld_acq_u32(&g_done[fx]) < s_target)   // usually 1 read
            __nanosleep(32);
    }
    __syncthreads();    // transpose visible + bias-publish ordered (block
                        // scope via barrier; device scope via done-flag)

    // ---- Vectorized reduction: 4 x red.global.add.v4.f32 per thread ----
    #pragma unroll
    for (int it = 0; it < 4; it++) {
        const int item = it * TFX + tid;     // 0..511 over (b, f-quad)
        const int b    = item >> 5;
        const int fg   = item & 31;
        const float4 v = *reinterpret_cast<const float4*>(&xb[b][fg * 4]);
        redg_add_v4(&y[b * F_ + fx * TFX + fg * 4], v);
    }
}

// ---------------------------------------------------------------------------
// Inputs (metadata order): x, mask, kv_idx, kv_key, kv_value,
//                          wq, bq, wk, bk, wv, bv, wo, bo
// ---------------------------------------------------------------------------
extern "C" void kernel_launch(void* const* d_in, const int* in_sizes, int n_in,
                              void* d_out, int out_size)
{
    const float* x        = (const float*)d_in[0];
    const int*   kv_idx   = (const int*)  d_in[2];
    const float* kv_value = (const float*)d_in[4];
    const float* wv       = (const float*)d_in[9];
    const float* bv       = (const float*)d_in[10];
    const float* wo       = (const float*)d_in[11];
    const float* bo       = (const float*)d_in[12];
    float* y = (float*)d_out;

    fused_kernel<<<dim3(NF, NK), TFX>>>(x, kv_idx, kv_value,
                                        wv, bv, wo, bo, y);
}

// round 17
// speedup vs baseline: 1.0817x; 1.0078x over previous
#include <cuda_runtime.h>
#include <cuda_bf16.h>

// Problem constants
#define B_  16
#define C_  4096
#define HD_ 1024   // H*D
#define F_  1024

// Tiling: grid = (NF, NK) = 256 blocks, 128 threads, one f-column per thread
#define NF  8
#define TFX 128
#define NK  32
#define TK  32

// Monotonic per-f-tile counters (never reset -> graph-replay-safe).
__device__ unsigned int g_done[NF];     // zero-init at module load
__device__ unsigned int g_ticket[NF];

__device__ __forceinline__ unsigned ld_acq_u32(const unsigned* p) {
    unsigned v;
    asm volatile("ld.global.acquire.gpu.u32 %0, [%1];" : "=r"(v) : "l"(p));
    return v;
}
__device__ __forceinline__ void redg_add_v4(float* p, float4 v) {
    asm volatile("red.global.add.v4.f32 [%0], {%1, %2, %3, %4};"
                 :: "l"(p), "f"(v.x), "f"(v.y), "f"(v.z), "f"(v.w)
                 : "memory");
}
__device__ __forceinline__ void ffma2(unsigned long long& d,
                                      unsigned long long a,
                                      unsigned long long b) {
    asm("fma.rn.f32x2 %0, %1, %2, %0;" : "+l"(d) : "l"(a), "l"(b));
}
__device__ __forceinline__ unsigned long long pack2(float lo, float hi) {
    unsigned long long r;
    asm("mov.b64 %0, {%1, %2};" : "=l"(r) : "f"(lo), "f"(hi));
    return r;
}
__device__ __forceinline__ float unpack_sum(unsigned long long v) {
    float lo, hi;
    asm("mov.b64 {%0, %1}, %2;" : "=f"(lo), "=f"(hi) : "l"(v));
    return lo + hi;
}
__device__ __forceinline__ float bfr(float v) {   // bf16 round-trip
    return __bfloat162float(__float2bfloat16(v));
}

// ---------------------------------------------------------------------------
// Single kernel. Attention degenerates (T=1 causal => softmax one-hot at
// rotated position 0) to v_sel[b] = bf16(kv_value[b, start_b]) -- or the
// fresh x@wv+bv row iff idx==0. Then y = v_sel @ wo + bo via 32-way split-K.
// Front-end: per-thread direct kv_idx load + single float4 gather; ONE
// barrier before the FMA loop. Epilogue: early-release bias publish (kx==0
// block, first thing) + smem transpose + VECTORIZED red.global.add.v4.f32
// (4 REDG ops/thread -> 4x less LTS atomic serialization than scalar).
// Best-measured config (R15): kernel 7.84us.
// ---------------------------------------------------------------------------
__global__ void __launch_bounds__(TFX)
fused_kernel(const float* __restrict__ x,
             const int*   __restrict__ kv_idx,
             const float* __restrict__ kv_value,
             const float* __restrict__ wv,
             const float* __restrict__ bv,
             const float* __restrict__ wo,
             const float* __restrict__ bo,
             float* __restrict__ y)
{
    const int fx  = blockIdx.x;
    const int kx  = blockIdx.y;
    const int tid = threadIdx.x;
    const int k0  = kx * TK;
    const int f   = fx * TFX + tid;

    __shared__ float    vs[B_][TK];         // bf16-rounded selected v slice
    __shared__ float    xb[B_][TFX];        // acc transpose buffer, 8 KB
    __shared__ int      s_new[B_];
    __shared__ unsigned s_target;

    // ---- Critical path first: this thread's single float4 gather ----
    const int  gb      = tid >> 3;          // b this thread gathers for
    const int  gq      = tid & 7;           // float4 index within TK slice
    const int  idxv    = __ldg(&kv_idx[gb]);
    const int  new_idx = idxv + 1;
    const int  start   = (new_idx <= C_) ? 0 : (new_idx & (C_ - 1));
    const bool use_new = (start == (idxv & (C_ - 1)));   // only when idx==0

    float4 gv = make_float4(0.f, 0.f, 0.f, 0.f);
    if (!use_new)
        gv = __ldg(reinterpret_cast<const float4*>(
                 kv_value + ((size_t)gb * C_ + start) * HD_ + k0) + gq);

    // ---- Writer publishes bias into y immediately (overwrites poison) ----
    if (kx == 0) {
        const float bias = __ldg(&bo[f]);
        #pragma unroll
        for (int b = 0; b < B_; b++)
            y[b * F_ + f] = bias;
        __threadfence();            // release bias stores device-wide
    } else if (tid == 0) {
        s_target = atomicAdd(&g_ticket[fx], 1u) / (NK - 1) + 1u;
    }

    // ---- Hoisted wo loads: overlap with gather latency ----
    float w[TK];
    #pragma unroll
    for (int k = 0; k < TK; k++)
        w[k] = __ldg(&wo[(size_t)(k0 + k) * F_ + f]);

    // ---- Store gathered slice (bf16-rounded) + bookkeeping ----
    if (!use_new) {
        float4 r;
        r.x = bfr(gv.x); r.y = bfr(gv.y); r.z = bfr(gv.z); r.w = bfr(gv.w);
        *reinterpret_cast<float4*>(&vs[gb][gq * 4]) = r;
    }
    if (gq == 0)
        s_new[gb] = use_new;

    // ONE barrier: vs visible + any_new flag + writer block fully fenced
    const int any_new = __syncthreads_or(use_new ? 1 : 0);

    if (kx == 0 && tid == 0)
        atomicAdd(&g_done[fx], 1u);          // release after block fenced

    if (any_new) {      // never taken for this input; kept for correctness
        for (int b = 0; b < B_; b++) {
            if (s_new[b] && tid < TK) {
                const int j = k0 + tid;
                float acc = bv[j];
                for (int ff = 0; ff < F_; ff++)
                    acc = fmaf(__ldg(&x[b * F_ + ff]),
                               __ldg(&wv[(size_t)ff * HD_ + j]), acc);
                vs[b][tid] = bfr(acc);
            }
        }
        __syncthreads();
    }

    // ---- Main loop: pure LDS + packed f32x2 FMA (wo already in regs) ----
    unsigned long long acc2[B_];
    #pragma unroll
    for (int b = 0; b < B_; b++) acc2[b] = 0ull;

    #pragma unroll
    for (int k4 = 0; k4 < TK; k4 += 4) {
        const unsigned long long wA = pack2(w[k4 + 0], w[k4 + 1]);
        const unsigned long long wB = pack2(w[k4 + 2], w[k4 + 3]);
        #pragma unroll
        for (int b = 0; b < B_; b++) {
            const float4 v = *reinterpret_cast<const float4*>(&vs[b][k4]);
            ffma2(acc2[b], pack2(v.x, v.y), wA);
            ffma2(acc2[b], pack2(v.z, v.w), wB);
        }
    }

    // ---- Transpose accs to smem so REDGs can be f-contiguous float4 ----
    #pragma unroll
    for (int b = 0; b < B_; b++)
        xb[b][tid] = unpack_sum(acc2[b]);    // conflict-free STS.32

    if (kx != 0 && tid == 0) {
        while (ld_acq_u32(&g_done[fx]) < s_target)   // usually 1 read
            __nanosleep(32);
    }
    __syncthreads();    // transpose visible + bias-publish ordered (block
                        // scope via barrier; device scope via done-flag)

    // ---- Vectorized reduction: 4 x red.global.add.v4.f32 per thread ----
    #pragma unroll
    for (int it = 0; it < 4; it++) {
        const int item = it * TFX + tid;     // 0..511 over (b, f-quad)
        const int b    = item >> 5;
        const int fg   = item & 31;
        const float4 v = *reinterpret_cast<const float4*>(&xb[b][fg * 4]);
        redg_add_v4(&y[b * F_ + fx * TFX + fg * 4], v);
    }
}

// ---------------------------------------------------------------------------
// Inputs (metadata order): x, mask, kv_idx, kv_key, kv_value,
//                          wq, bq, wk, bk, wv, bv, wo, bo
// ---------------------------------------------------------------------------
extern "C" void kernel_launch(void* const* d_in, const int* in_sizes, int n_in,
                              void* d_out, int out_size)
{
    const float* x        = (const float*)d_in[0];
    const int*   kv_idx   = (const int*)  d_in[2];
    const float* kv_value = (const float*)d_in[4];
    const float* wv       = (const float*)d_in[9];
    const float* bv       = (const float*)d_in[10];
    const float* wo       = (const float*)d_in[11];
    const float* bo       = (const float*)d_in[12];
    float* y = (float*)d_out;

    fused_kernel<<<dim3(NF, NK), TFX>>>(x, kv_idx, kv_value,
                                        wv, bv, wo, bo, y);
}